// round 1
// baseline (speedup 1.0000x reference)
#include <cuda_runtime.h>
#include <cstddef>

// GRU: B=2048(derived), T=1024, D=6, H=48; y = fc(GRU(x))
// Mapping: 48 threads per batch row (thread owns h index i), ROWS rows/block.
// W_hh in registers as f32x2 pairs; h double-buffered in shared; fma.rn.f32x2 everywhere.

#define T_SEQ 1024
#define D_IN  6
#define HDIM  48
#define ROWS  2
#define NTHR  (ROWS * HDIM)

__device__ __forceinline__ float2 ffma2(float2 a, float2 b, float2 c) {
    union U { float2 f; unsigned long long u; };
    U ua, ub, uc, ud;
    ua.f = a; ub.f = b; uc.f = c;
    asm("fma.rn.f32x2 %0, %1, %2, %3;" : "=l"(ud.u) : "l"(ua.u), "l"(ub.u), "l"(uc.u));
    return ud.f;
}

__device__ __forceinline__ float fast_sigmoid(float x) {
    float e = __expf(-x);                       // MUFU ex2 path, ~1 ulp for sane range
    return __fdividef(1.0f, 1.0f + e);          // x << 0: e=inf -> 0  (correct limit)
}

__device__ __forceinline__ float fast_tanh(float x) {
    float a = fabsf(x);
    float e = __expf(2.0f * a);                 // overflow -> inf is fine
    float r = 1.0f - __fdividef(2.0f, e + 1.0f);
    return copysignf(r, x);
}

__global__ void __launch_bounds__(NTHR, 1)
gru_fused_kernel(const float* __restrict__ x,
                 const float* __restrict__ W_ih,   // [144, 6]
                 const float* __restrict__ W_hh,   // [144, 48]
                 const float* __restrict__ b_ih,   // [144]
                 const float* __restrict__ b_hh,   // [144]
                 const float* __restrict__ fc_w,   // [6, 48]
                 const float* __restrict__ fc_b,   // [6]
                 float* __restrict__ y,            // [B, T, 6]
                 int B)
{
    __shared__ __align__(16) float hbuf[2][ROWS][HDIM];
    __shared__ __align__(16) float xbuf[2][ROWS][8];

    const int tid = threadIdx.x;
    const int r   = tid / HDIM;          // row within block
    const int i   = tid - r * HDIM;      // h index 0..47
    const int b   = blockIdx.x * ROWS + r;
    const bool valid = (b < B);

    // ---- load recurrent weights into registers as f32x2 pairs over k ----
    float2 wr[24], wz[24], wn[24];
    {
        const float4* p0 = reinterpret_cast<const float4*>(W_hh + (size_t)(0 * HDIM + i) * HDIM);
        const float4* p1 = reinterpret_cast<const float4*>(W_hh + (size_t)(1 * HDIM + i) * HDIM + 0);
        const float4* p2 = reinterpret_cast<const float4*>(W_hh + (size_t)(2 * HDIM + i) * HDIM + 0);
        // note: (g*48+i)*48 floats -> byte offset multiple of 192 -> 16B aligned
        #pragma unroll
        for (int q = 0; q < 12; q++) {
            float4 v;
            v = p0[q]; wr[2*q] = make_float2(v.x, v.y); wr[2*q+1] = make_float2(v.z, v.w);
            v = p1[q]; wz[2*q] = make_float2(v.x, v.y); wz[2*q+1] = make_float2(v.z, v.w);
            v = p2[q]; wn[2*q] = make_float2(v.x, v.y); wn[2*q+1] = make_float2(v.z, v.w);
        }
    }
    // ---- input-projection weights (rows of length 6 -> 3 pairs each) ----
    float2 wir[3], wiz[3], win[3];
    {
        const float2* pr = reinterpret_cast<const float2*>(W_ih + (size_t)(0 * HDIM + i) * D_IN);
        const float2* pz = reinterpret_cast<const float2*>(W_ih + (size_t)(1 * HDIM + i) * D_IN);
        const float2* pn = reinterpret_cast<const float2*>(W_ih + (size_t)(2 * HDIM + i) * D_IN);
        #pragma unroll
        for (int j = 0; j < 3; j++) { wir[j] = pr[j]; wiz[j] = pz[j]; win[j] = pn[j]; }
    }
    const float brr = b_ih[i]            + b_hh[i];
    const float bzz = b_ih[HDIM + i]     + b_hh[HDIM + i];
    const float bin = b_ih[2 * HDIM + i];
    const float bhn = b_hh[2 * HDIM + i];

    // ---- fc: lane (d = i/8, c = i%8) computes partial over k = c*6 .. c*6+5 ----
    const int d_fc = i >> 3;
    const int c_fc = i & 7;
    float2 fw[3];
    {
        const float2* p = reinterpret_cast<const float2*>(fc_w + (size_t)d_fc * HDIM + c_fc * 6);
        fw[0] = p[0]; fw[1] = p[1]; fw[2] = p[2];
    }
    const float fb = fc_b[d_fc];

    // ---- init state ----
    hbuf[0][r][i] = 0.0f;
    const float* xrow = x + (size_t)b * T_SEQ * D_IN;
    float*       yrow = y + (size_t)b * T_SEQ * D_IN;
    if (i < D_IN) xbuf[0][r][i] = valid ? xrow[i] : 0.0f;
    float hcur = 0.0f;
    __syncthreads();

    int p = 0;
    const float2 z2 = make_float2(0.0f, 0.0f);

    for (int t = 0; t < T_SEQ; t++) {
        // prefetch next x (consumed after the barrier below)
        float xn = 0.0f;
        if (i < D_IN && (t + 1) < T_SEQ && valid) xn = xrow[(size_t)(t + 1) * D_IN + i];

        // ---- gi = W_ih[g*48+i, :] . x_t ----
        const float2* xp = reinterpret_cast<const float2*>(xbuf[p][r]);
        float2 a_r = z2, a_z = z2, a_in = z2, a_gn = z2;
        #pragma unroll
        for (int j = 0; j < 3; j++) {
            float2 xv = xp[j];
            a_r  = ffma2(wir[j], xv, a_r);
            a_z  = ffma2(wiz[j], xv, a_z);
            a_in = ffma2(win[j], xv, a_in);
        }

        // ---- gh = W_hh[g*48+i, :] . h_{t-1}  (broadcast LDS.128 reads) ----
        const float4* h4 = reinterpret_cast<const float4*>(hbuf[p][r]);
        #pragma unroll
        for (int q = 0; q < 12; q++) {
            float4 hv = h4[q];
            float2 h01 = make_float2(hv.x, hv.y);
            float2 h23 = make_float2(hv.z, hv.w);
            a_r  = ffma2(wr[2*q], h01, a_r);   a_r  = ffma2(wr[2*q+1], h23, a_r);
            a_z  = ffma2(wz[2*q], h01, a_z);   a_z  = ffma2(wz[2*q+1], h23, a_z);
            a_gn = ffma2(wn[2*q], h01, a_gn);  a_gn = ffma2(wn[2*q+1], h23, a_gn);
        }

        // ---- fused fc for the PREVIOUS step's h (currently in hbuf[p]) -> y_{t-1} ----
        {
            const float2* hc = reinterpret_cast<const float2*>(hbuf[p][r] + c_fc * 6);
            float2 acc = ffma2(fw[0], hc[0], z2);
            acc = ffma2(fw[1], hc[1], acc);
            acc = ffma2(fw[2], hc[2], acc);
            float part = acc.x + acc.y;
            part += __shfl_down_sync(0xffffffffu, part, 4, 8);
            part += __shfl_down_sync(0xffffffffu, part, 2, 8);
            part += __shfl_down_sync(0xffffffffu, part, 1, 8);
            if (c_fc == 0 && t > 0 && valid)
                yrow[(size_t)(t - 1) * D_IN + d_fc] = part + fb;
        }

        // ---- gates + state update ----
        float sr = a_r.x + a_r.y + brr;
        float sz = a_z.x + a_z.y + bzz;
        float rg = fast_sigmoid(sr);
        float zg = fast_sigmoid(sz);
        float ng = fast_tanh((a_in.x + a_in.y + bin) + rg * (a_gn.x + a_gn.y + bhn));
        hcur = ng + zg * (hcur - ng);          // (1-z)*n + z*h

        hbuf[p ^ 1][r][i] = hcur;
        if (i < D_IN) xbuf[p ^ 1][r][i] = xn;
        __syncthreads();
        p ^= 1;
    }

    // ---- fc for the final step (h_{T-1} in hbuf[p]) ----
    {
        const float2* hc = reinterpret_cast<const float2*>(hbuf[p][r] + c_fc * 6);
        float2 acc = ffma2(fw[0], hc[0], z2);
        acc = ffma2(fw[1], hc[1], acc);
        acc = ffma2(fw[2], hc[2], acc);
        float part = acc.x + acc.y;
        part += __shfl_down_sync(0xffffffffu, part, 4, 8);
        part += __shfl_down_sync(0xffffffffu, part, 2, 8);
        part += __shfl_down_sync(0xffffffffu, part, 1, 8);
        if (c_fc == 0 && valid)
            yrow[(size_t)(T_SEQ - 1) * D_IN + d_fc] = part + fb;
    }
}

extern "C" void kernel_launch(void* const* d_in, const int* in_sizes, int n_in,
                              void* d_out, int out_size)
{
    const float* x    = (const float*)d_in[0];
    const float* W_ih = (const float*)d_in[1];
    const float* W_hh = (const float*)d_in[2];
    const float* b_ih = (const float*)d_in[3];
    const float* b_hh = (const float*)d_in[4];
    const float* fc_w = (const float*)d_in[5];
    const float* fc_b = (const float*)d_in[6];
    float* y = (float*)d_out;

    int B = in_sizes[0] / (T_SEQ * D_IN);
    int blocks = (B + ROWS - 1) / ROWS;
    gru_fused_kernel<<<blocks, NTHR>>>(x, W_ih, W_hh, b_ih, b_hh, fc_w, fc_b, y, B);
}

// round 2
// speedup vs baseline: 1.2651x; 1.2651x over previous
#include <cuda_runtime.h>
#include <cstddef>

// GRU (B rows, T=1024, D=6, H=48) + fused FC.
// Block = 96 threads, 2 batch rows. Split-k: thread (s = tid/48, i = tid%48)
// computes k-half s of all 3 gate dots for output i, for BOTH rows (weight reuse).
// Combine role: thread (r = tid/48, i) finishes gates for (row r, output i).
// Two barriers per step; single-buffered smem (phases are disjoint).

#define T_SEQ 1024
#define D_IN  6
#define HDIM  48
#define KH    24          // k-half length
#define R     2
#define NTHR  96

__device__ __forceinline__ float2 ffma2(float2 a, float2 b, float2 c) {
    union U { float2 f; unsigned long long u; };
    U ua, ub, uc, ud;
    ua.f = a; ub.f = b; uc.f = c;
    asm("fma.rn.f32x2 %0, %1, %2, %3;" : "=l"(ud.u) : "l"(ua.u), "l"(ub.u), "l"(uc.u));
    return ud.f;
}

__device__ __forceinline__ float fast_sigmoid(float x) {
    float e = __expf(-x);
    return __fdividef(1.0f, 1.0f + e);
}
__device__ __forceinline__ float fast_tanh(float x) {
    float a = fabsf(x);
    float e = __expf(2.0f * a);
    float r = 1.0f - __fdividef(2.0f, e + 1.0f);
    return copysignf(r, x);
}

__global__ void __launch_bounds__(NTHR, 5)
gru_fused_kernel(const float* __restrict__ x,
                 const float* __restrict__ W_ih,   // [144, 6]
                 const float* __restrict__ W_hh,   // [144, 48]
                 const float* __restrict__ b_ih,   // [144]
                 const float* __restrict__ b_hh,   // [144]
                 const float* __restrict__ fc_w,   // [6, 48]
                 const float* __restrict__ fc_b,   // [6]
                 float* __restrict__ y,            // [B, T, 6]
                 int B)
{
    __shared__ __align__(16) float h_s[R][HDIM];          // h_{t-1} / h_t
    __shared__ __align__(16) float p_s[2][R][4][HDIM];    // [khalf][row][{r,z,ghn,gin}][i]
    __shared__ __align__(16) float x_s[R][8];              // x_t per row

    const int tid = threadIdx.x;
    const int s   = tid / HDIM;          // k-half (computer role)  0/1
    const int i   = tid - s * HDIM;      // output index 0..47 (both roles)
    const int rc  = s;                   // combiner-role row (same split)
    const int b0  = blockIdx.x * R;

    const bool valid0 = (b0 + 0) < B;
    const bool valid1 = (b0 + 1) < B;
    const bool validc = (b0 + rc) < B;   // combiner/fc row validity

    // ---- computer weights: W_hh[g*48+i][s*24 .. s*24+23] as 12 float2 / gate ----
    float2 whr[12], whz[12], whn[12];
    {
        const float4* pr = reinterpret_cast<const float4*>(W_hh + ((size_t)(0 * HDIM + i) * HDIM + s * KH));
        const float4* pz = reinterpret_cast<const float4*>(W_hh + ((size_t)(1 * HDIM + i) * HDIM + s * KH));
        const float4* pn = reinterpret_cast<const float4*>(W_hh + ((size_t)(2 * HDIM + i) * HDIM + s * KH));
        #pragma unroll
        for (int q = 0; q < 6; q++) {
            float4 v;
            v = pr[q]; whr[2*q] = make_float2(v.x, v.y); whr[2*q+1] = make_float2(v.z, v.w);
            v = pz[q]; whz[2*q] = make_float2(v.x, v.y); whz[2*q+1] = make_float2(v.z, v.w);
            v = pn[q]; whn[2*q] = make_float2(v.x, v.y); whn[2*q+1] = make_float2(v.z, v.w);
        }
    }
    // gi weights: W_ih[g*48+i][s*3 .. s*3+2]
    float wir[3], wiz[3], win[3];
    #pragma unroll
    for (int j = 0; j < 3; j++) {
        wir[j] = W_ih[(size_t)(0 * HDIM + i) * D_IN + s * 3 + j];
        wiz[j] = W_ih[(size_t)(1 * HDIM + i) * D_IN + s * 3 + j];
        win[j] = W_ih[(size_t)(2 * HDIM + i) * D_IN + s * 3 + j];
    }

    // ---- combiner biases (for output i) ----
    const float brz_r = b_ih[i]            + b_hh[i];
    const float brz_z = b_ih[HDIM + i]     + b_hh[HDIM + i];
    const float bin   = b_ih[2 * HDIM + i];
    const float bhn   = b_hh[2 * HDIM + i];

    // ---- fc weights: thread (rc, i): d = i>>3, c = i&7, k = 6c..6c+5 ----
    const int d_fc = i >> 3;
    const int c_fc = i & 7;
    float2 fw[3];
    {
        const float2* p = reinterpret_cast<const float2*>(fc_w + (size_t)d_fc * HDIM + c_fc * 6);
        fw[0] = p[0]; fw[1] = p[1]; fw[2] = p[2];
    }
    const float fb = fc_b[d_fc];

    // ---- init ----
    float hcur = 0.0f;                       // combiner-owned h for (rc, i)
    h_s[rc][i] = 0.0f;
    if (tid < R * D_IN) {
        int rr = tid / D_IN, dd = tid - rr * D_IN;
        x_s[rr][dd] = ((b0 + rr) < B) ? x[((size_t)(b0 + rr) * T_SEQ) * D_IN + dd] : 0.0f;
    }
    const float* xg = x + ((size_t)b0 * T_SEQ) * D_IN;      // row-pair base
    float*       yc = y + ((size_t)(b0 + rc) * T_SEQ) * D_IN;
    __syncthreads();

    const float2 z2 = make_float2(0.0f, 0.0f);

    for (int t = 0; t < T_SEQ; t++) {
        // ---- prefetch x[t+1] (one float per thread, first 12 threads) ----
        float xn = 0.0f;
        if (tid < R * D_IN && (t + 1) < T_SEQ) {
            int rr = tid / D_IN, dd = tid - rr * D_IN;
            if ((b0 + rr) < B) xn = xg[((size_t)rr * T_SEQ + (t + 1)) * D_IN + dd];
        }

        // ================= P1: partial dot products (both rows) =================
        #pragma unroll
        for (int r = 0; r < R; r++) {
            float2 a_r = z2, a_z = z2, a_n = z2;
            float  g_r = 0.f, g_z = 0.f, g_n = 0.f;
            // gi partials over this thread's D-half
            #pragma unroll
            for (int j = 0; j < 3; j++) {
                float xv = x_s[r][s * 3 + j];
                g_r = fmaf(wir[j], xv, g_r);
                g_z = fmaf(wiz[j], xv, g_z);
                g_n = fmaf(win[j], xv, g_n);
            }
            // gh partials over this thread's k-half
            const float4* h4 = reinterpret_cast<const float4*>(&h_s[r][s * KH]);
            #pragma unroll
            for (int q = 0; q < 6; q++) {
                float4 hv = h4[q];
                float2 h01 = make_float2(hv.x, hv.y);
                float2 h23 = make_float2(hv.z, hv.w);
                a_r = ffma2(whr[2*q], h01, a_r); a_r = ffma2(whr[2*q+1], h23, a_r);
                a_z = ffma2(whz[2*q], h01, a_z); a_z = ffma2(whz[2*q+1], h23, a_z);
                a_n = ffma2(whn[2*q], h01, a_n); a_n = ffma2(whn[2*q+1], h23, a_n);
            }
            p_s[s][r][0][i] = a_r.x + a_r.y + g_r;   // r partial (gi+gh mixed: both add)
            p_s[s][r][1][i] = a_z.x + a_z.y + g_z;   // z partial
            p_s[s][r][2][i] = a_n.x + a_n.y;         // gh_n partial (kept separate)
            p_s[s][r][3][i] = g_n;                    // gi_n partial
        }

        // ---- fused fc on h_{t-1} (still valid until BAR1) ----
        if (t > 0) {
            const float2* hc = reinterpret_cast<const float2*>(&h_s[rc][c_fc * 6]);
            float2 acc = ffma2(fw[0], hc[0], z2);
            acc = ffma2(fw[1], hc[1], acc);
            acc = ffma2(fw[2], hc[2], acc);
            float part = acc.x + acc.y;
            part += __shfl_down_sync(0xffffffffu, part, 4, 8);
            part += __shfl_down_sync(0xffffffffu, part, 2, 8);
            part += __shfl_down_sync(0xffffffffu, part, 1, 8);
            if (c_fc == 0 && validc)
                yc[(size_t)(t - 1) * D_IN + d_fc] = part + fb;
        }
        __syncthreads();   // BAR1: partials ready; h_{t-1} no longer needed

        // ================= P2: combine + gates for (rc, i) =================
        {
            float sr  = p_s[0][rc][0][i] + p_s[1][rc][0][i] + brz_r;
            float sz  = p_s[0][rc][1][i] + p_s[1][rc][1][i] + brz_z;
            float ghn = p_s[0][rc][2][i] + p_s[1][rc][2][i] + bhn;
            float gin = p_s[0][rc][3][i] + p_s[1][rc][3][i] + bin;
            float rg = fast_sigmoid(sr);
            float zg = fast_sigmoid(sz);
            float ng = fast_tanh(gin + rg * ghn);
            hcur = ng + zg * (hcur - ng);
            h_s[rc][i] = hcur;
        }
        if (tid < R * D_IN) {
            int rr = tid / D_IN, dd = tid - rr * D_IN;
            x_s[rr][dd] = xn;
        }
        __syncthreads();   // BAR2: h_t + x_{t+1} visible
    }

    // ---- fc for the final h_{T-1} ----
    {
        const float2* hc = reinterpret_cast<const float2*>(&h_s[rc][c_fc * 6]);
        float2 acc = ffma2(fw[0], hc[0], z2);
        acc = ffma2(fw[1], hc[1], acc);
        acc = ffma2(fw[2], hc[2], acc);
        float part = acc.x + acc.y;
        part += __shfl_down_sync(0xffffffffu, part, 4, 8);
        part += __shfl_down_sync(0xffffffffu, part, 2, 8);
        part += __shfl_down_sync(0xffffffffu, part, 1, 8);
        if (c_fc == 0 && validc)
            yc[(size_t)(T_SEQ - 1) * D_IN + d_fc] = part + fb;
    }
    (void)valid0; (void)valid1;
}

extern "C" void kernel_launch(void* const* d_in, const int* in_sizes, int n_in,
                              void* d_out, int out_size)
{
    const float* x    = (const float*)d_in[0];
    const float* W_ih = (const float*)d_in[1];
    const float* W_hh = (const float*)d_in[2];
    const float* b_ih = (const float*)d_in[3];
    const float* b_hh = (const float*)d_in[4];
    const float* fc_w = (const float*)d_in[5];
    const float* fc_b = (const float*)d_in[6];
    float* y = (float*)d_out;

    int B = in_sizes[0] / (T_SEQ * D_IN);
    int blocks = (B + R - 1) / R;
    gru_fused_kernel<<<blocks, NTHR>>>(x, W_ih, W_hh, b_ih, b_hh, fc_w, fc_b, y, B);
}